// round 3
// baseline (speedup 1.0000x reference)
#include <cuda_runtime.h>
#include <cstdint>

// Problem constants
#define BB 64
#define CC 64
#define TT 2000
#define PL 200
#define STRD 100
#define EE 512
#define PP 19
#define NROWS (BB*CC*PP)   // 77824
#define EPSV 1e-5f

// Scratch (allowed: __device__ globals)
__device__ float g_mean[NROWS];
__device__ float g_inv[NROWS];
__device__ float g_wsum[EE];

// ---------------- wsum: rowsum of W over l ----------------
__global__ void wsum_kernel(const float* __restrict__ W) {
    int d = blockIdx.x * blockDim.x + threadIdx.x;
    if (d < EE) {
        const float* wr = W + (size_t)d * PL;
        float s = 0.f;
        #pragma unroll 8
        for (int l = 0; l < PL; ++l) s += wr[l];
        g_wsum[d] = s;
    }
}

// ---------------- stats + patches copy ----------------
// one warp per row (77824 rows)
__global__ void stats_kernel(const float* __restrict__ x,
                             float* __restrict__ patches,
                             float* __restrict__ mean_out,
                             float* __restrict__ std_out) {
    int warp = (blockIdx.x * blockDim.x + threadIdx.x) >> 5;
    int lane = threadIdx.x & 31;
    if (warp >= NROWS) return;
    int bc = warp / PP;
    int p  = warp % PP;
    const float* src = x + (size_t)bc * TT + p * STRD;
    float* dst = patches + (size_t)warp * PL;

    float s = 0.f, s2 = 0.f;
    #pragma unroll
    for (int i = 0; i < 7; ++i) {
        int l = lane + i * 32;
        if (l < PL) {
            float v = src[l];
            s += v; s2 += v * v;
            dst[l] = v;
        }
    }
    #pragma unroll
    for (int off = 16; off; off >>= 1) {
        s  += __shfl_xor_sync(0xffffffffu, s,  off);
        s2 += __shfl_xor_sync(0xffffffffu, s2, off);
    }
    if (lane == 0) {
        float mean = s * (1.f / PL);
        float var  = (s2 - s * mean) * (1.f / (PL - 1));
        float sd   = sqrtf(fmaxf(var, 0.f));
        mean_out[warp] = mean;
        std_out[warp]  = sd;
        g_mean[warp] = mean;
        g_inv[warp]  = 1.f / (sd + EPSV);
    }
}

// ---------------- GEMM 64x64 tile, BK=8, fp32 ----------------
// emb[row,d] = inv[row]*(sum_l x_patch[row,l]*W[d,l] - mean[row]*wsum[d]) + b[d] + pe[p,d]
// then *= gain[subj[batch], d]
__global__ __launch_bounds__(256) void gemm_kernel(
    const float* __restrict__ x, const float* __restrict__ W,
    const float* __restrict__ bias, const float* __restrict__ pos,
    const int* __restrict__ subj, const float* __restrict__ gain,
    float* __restrict__ emb)
{
    __shared__ float sA[8][68];
    __shared__ float sB[8][68];
    const int tid  = threadIdx.x;
    const int row0 = blockIdx.x * 64;
    const int n0   = blockIdx.y * 64;

    // loader mapping: 4 threads per row, each loads float2
    const int lr = tid >> 2;            // 0..63
    const int lq = (tid & 3) * 2;       // 0,2,4,6
    const int arow = row0 + lr;
    const int abc = arow / PP, ap = arow % PP;
    const float* aptr = x + (size_t)abc * TT + ap * STRD + lq;
    const float* bptr = W + (size_t)(n0 + lr) * PL + lq;

    const int ty = tid >> 4;   // 0..15
    const int tx = tid & 15;   // 0..15

    float acc[4][4] = {};

    for (int k0 = 0; k0 < PL; k0 += 8) {
        float2 av = *(const float2*)(aptr + k0);
        float2 bv = *(const float2*)(bptr + k0);
        __syncthreads();
        sA[lq][lr]     = av.x;
        sA[lq + 1][lr] = av.y;
        sB[lq][lr]     = bv.x;
        sB[lq + 1][lr] = bv.y;
        __syncthreads();
        #pragma unroll
        for (int kk = 0; kk < 8; ++kk) {
            float4 a4 = *(const float4*)&sA[kk][ty * 4];
            float4 b4 = *(const float4*)&sB[kk][tx * 4];
            acc[0][0] += a4.x * b4.x; acc[0][1] += a4.x * b4.y;
            acc[0][2] += a4.x * b4.z; acc[0][3] += a4.x * b4.w;
            acc[1][0] += a4.y * b4.x; acc[1][1] += a4.y * b4.y;
            acc[1][2] += a4.y * b4.z; acc[1][3] += a4.y * b4.w;
            acc[2][0] += a4.z * b4.x; acc[2][1] += a4.z * b4.y;
            acc[2][2] += a4.z * b4.z; acc[2][3] += a4.z * b4.w;
            acc[3][0] += a4.w * b4.x; acc[3][1] += a4.w * b4.y;
            acc[3][2] += a4.w * b4.z; acc[3][3] += a4.w * b4.w;
        }
    }

    #pragma unroll
    for (int i = 0; i < 4; ++i) {
        int r = row0 + ty * 4 + i;
        float mv = g_mean[r], iv = g_inv[r];
        int rbc = r / PP, rp = r % PP;
        int batch = rbc >> 6;                 // / CC
        int sid = subj[batch];
        const float* gn = gain + (size_t)sid * EE;
        const float* pe = pos + (size_t)rp * EE;
        float* orow = emb + (size_t)r * EE;
        #pragma unroll
        for (int j = 0; j < 4; ++j) {
            int d = n0 + tx * 4 + j;
            float val = iv * (acc[i][j] - mv * g_wsum[d]) + bias[d] + pe[d];
            orow[d] = val * gn[d];
        }
    }
}

// ---------------- JAX threefry2x32, partitionable mode ----------------
__device__ __forceinline__ void threefry(uint32_t k0, uint32_t k1,
                                         uint32_t x0, uint32_t x1,
                                         uint32_t& o0, uint32_t& o1) {
    uint32_t ks2 = k0 ^ k1 ^ 0x1BD11BDAu;
    x0 += k0; x1 += k1;
#define TF_RND(r) { x0 += x1; x1 = (x1 << r) | (x1 >> (32 - r)); x1 ^= x0; }
    TF_RND(13) TF_RND(15) TF_RND(26) TF_RND(6)  x0 += k1;  x1 += ks2 + 1u;
    TF_RND(17) TF_RND(29) TF_RND(16) TF_RND(24) x0 += ks2; x1 += k0 + 2u;
    TF_RND(13) TF_RND(15) TF_RND(26) TF_RND(6)  x0 += k0;  x1 += k1 + 3u;
    TF_RND(17) TF_RND(29) TF_RND(16) TF_RND(24) x0 += k1;  x1 += ks2 + 4u;
    TF_RND(13) TF_RND(15) TF_RND(26) TF_RND(6)  x0 += ks2; x1 += k0 + 5u;
#undef TF_RND
    o0 = x0; o1 = x1;
}

// partitionable 32-bit random_bits: counter = flat index (hi=0), out = o0 ^ o1
__device__ __forceinline__ uint32_t prf32(uint32_t k0, uint32_t k1, uint32_t i) {
    uint32_t o0, o1;
    threefry(k0, k1, 0u, i, o0, o1);
    return o0 ^ o1;
}

__device__ __forceinline__ float u01(uint32_t bits) {
    return __uint_as_float((bits >> 9) | 0x3f800000u) - 1.0f;
}

__global__ void mask_kernel(float* __restrict__ mout) {
    int row = blockIdx.x * blockDim.x + threadIdx.x;
    if (row >= BB * CC) return;
    // key(42) = (0,42)
    // partitionable (fold-like) split: child_i = full threefry output with counter i
    //   k1 = threefry((0,42), 0, 0) -> (k1a, k1b)
    //   k2 = threefry((0,42), 0, 1) -> (k2a, k2b)
    uint32_t k1a, k1b, k2a, k2b;
    threefry(0u, 42u, 0u, 0u, k1a, k1b);
    threefry(0u, 42u, 0u, 1u, k2a, k2b);

    float r0 = u01(prf32(k2a, k2b, (uint32_t)(row * 3 + 0)));
    float r1 = u01(prf32(k2a, k2b, (uint32_t)(row * 3 + 1)));
    float r2 = u01(prf32(k2a, k2b, (uint32_t)(row * 3 + 2)));

    bool m[PP];
    #pragma unroll
    for (int j = 0; j < PP; ++j)
        m[j] = u01(prf32(k1a, k1b, (uint32_t)(row * PP + j))) < 0.1f;

    if (r0 < 0.5f)  { for (int j = PP - 1; j >= 1; --j) m[j] = m[j] | m[j - 1]; }
    if (r1 < 0.5f)  { for (int j = 0; j < PP - 1; ++j) m[j] = m[j] | m[j + 1]; }
    if (r2 < 0.25f) { for (int j = 0; j < PP - 1; ++j) m[j] = m[j] | m[j + 1]; }

    float* dst = mout + (size_t)row * PP;
    #pragma unroll
    for (int j = 0; j < PP; ++j) dst[j] = m[j] ? 1.0f : 0.0f;
}

// ---------------- launch ----------------
extern "C" void kernel_launch(void* const* d_in, const int* in_sizes, int n_in,
                              void* d_out, int out_size) {
    const float* x    = (const float*)d_in[0];
    const int*   subj = (const int*)  d_in[1];
    const float* W    = (const float*)d_in[2];
    const float* bias = (const float*)d_in[3];
    const float* pos  = (const float*)d_in[4];
    const float* gain = (const float*)d_in[5];

    float* out      = (float*)d_out;
    float* emb      = out;                               // 77824*512
    float* patches  = emb + (size_t)NROWS * EE;          // 77824*200
    float* mfloat   = patches + (size_t)NROWS * PL;      // 77824
    float* mean_out = mfloat + NROWS;                    // 77824
    float* std_out  = mean_out + NROWS;                  // 77824

    wsum_kernel<<<2, 256>>>(W);
    stats_kernel<<<NROWS / 8, 256>>>(x, patches, mean_out, std_out);
    dim3 g(NROWS / 64, EE / 64);
    gemm_kernel<<<g, 256>>>(x, W, bias, pos, subj, gain, emb);
    mask_kernel<<<(BB * CC) / 256, 256>>>(mfloat);
}

// round 4
// speedup vs baseline: 1.5673x; 1.5673x over previous
#include <cuda_runtime.h>
#include <cstdint>

// Problem constants
#define BB 64
#define CC 64
#define TT 2000
#define PL 200
#define STRD 100
#define EE 512
#define PP 19
#define NROWS (BB*CC*PP)   // 77824
#define EPSV 1e-5f

// Scratch (allowed: __device__ globals)
__device__ float g_mean[NROWS];
__device__ float g_inv[NROWS];
__device__ float g_wsum[EE];

// ---------------- wsum: rowsum of W over l ----------------
__global__ void wsum_kernel(const float* __restrict__ W) {
    int d = blockIdx.x * blockDim.x + threadIdx.x;
    if (d < EE) {
        const float* wr = W + (size_t)d * PL;
        float s = 0.f;
        #pragma unroll 8
        for (int l = 0; l < PL; ++l) s += wr[l];
        g_wsum[d] = s;
    }
}

// ---------------- stats + patches copy ----------------
__global__ void stats_kernel(const float* __restrict__ x,
                             float* __restrict__ patches,
                             float* __restrict__ mean_out,
                             float* __restrict__ std_out) {
    int warp = (blockIdx.x * blockDim.x + threadIdx.x) >> 5;
    int lane = threadIdx.x & 31;
    if (warp >= NROWS) return;
    int bc = warp / PP;
    int p  = warp % PP;
    const float* src = x + (size_t)bc * TT + p * STRD;
    float* dst = patches + (size_t)warp * PL;

    float s = 0.f, s2 = 0.f;
    #pragma unroll
    for (int i = 0; i < 7; ++i) {
        int l = lane + i * 32;
        if (l < PL) {
            float v = src[l];
            s += v; s2 += v * v;
            dst[l] = v;
        }
    }
    #pragma unroll
    for (int off = 16; off; off >>= 1) {
        s  += __shfl_xor_sync(0xffffffffu, s,  off);
        s2 += __shfl_xor_sync(0xffffffffu, s2, off);
    }
    if (lane == 0) {
        float mean = s * (1.f / PL);
        float var  = (s2 - s * mean) * (1.f / (PL - 1));
        float sd   = sqrtf(fmaxf(var, 0.f));
        mean_out[warp] = mean;
        std_out[warp]  = sd;
        g_mean[warp] = mean;
        g_inv[warp]  = 1.f / (sd + EPSV);
    }
}

// ---------------- tf32 tensor-core GEMM ----------------
// C[row,d] = sum_l x_patch[row,l] * W[d,l]  (raw x; normalization folded into epilogue)
// emb = iv*(C - mv*wsum[d]) + b[d] + pe[rp,d], then * gain
__device__ __forceinline__ uint32_t f2tf32(float x) {
    uint32_t r;
    asm("cvt.rna.tf32.f32 %0, %1;" : "=r"(r) : "f"(x));
    return r;
}

__device__ __forceinline__ void mma_tf32(float* d, const uint32_t* a,
                                         const uint32_t* b, const float* c) {
    asm volatile(
        "mma.sync.aligned.m16n8k8.row.col.f32.tf32.tf32.f32 "
        "{%0,%1,%2,%3}, {%4,%5,%6,%7}, {%8,%9}, {%10,%11,%12,%13};\n"
        : "=f"(d[0]), "=f"(d[1]), "=f"(d[2]), "=f"(d[3])
        : "r"(a[0]), "r"(a[1]), "r"(a[2]), "r"(a[3]),
          "r"(b[0]), "r"(b[1]),
          "f"(c[0]), "f"(c[1]), "f"(c[2]), "f"(c[3]));
}

#define BM 128
#define BN 128
#define BKP 12   // BK=8 padded to 12 floats -> conflict-free fragment reads

__global__ __launch_bounds__(256, 1) void gemm_tc_kernel(
    const float* __restrict__ x, const float* __restrict__ W,
    const float* __restrict__ bias, const float* __restrict__ pos,
    const int* __restrict__ subj, const float* __restrict__ gain,
    float* __restrict__ emb)
{
    __shared__ uint32_t sA[BM][BKP];
    __shared__ uint32_t sB[BN][BKP];

    const int tid  = threadIdx.x;
    const int wid  = tid >> 5;
    const int lane = tid & 31;
    const int g    = lane >> 2;   // 0..7
    const int tg   = lane & 3;    // 0..3
    const int wm   = wid >> 1;    // 0..3 : warp M tile (32 rows)
    const int wn   = wid & 1;     // 0..1 : warp N tile (64 cols)

    const int row0 = blockIdx.x * BM;
    const int n0   = blockIdx.y * BN;

    // global loaders: 2 threads per tile row, float4 each
    const int lrow = tid >> 1;
    const int lk   = (tid & 1) * 4;
    const int arow = row0 + lrow;
    const int abc  = arow / PP, ap = arow % PP;
    const float* aptr = x + (size_t)abc * TT + ap * STRD + lk;
    const float* bptr = W + (size_t)(n0 + lrow) * PL + lk;

    float acc[2][8][4];
    #pragma unroll
    for (int mt = 0; mt < 2; ++mt)
        #pragma unroll
        for (int nt = 0; nt < 8; ++nt)
            #pragma unroll
            for (int q = 0; q < 4; ++q) acc[mt][nt][q] = 0.f;

    float4 av = *(const float4*)aptr;
    float4 bv = *(const float4*)bptr;

    for (int k0 = 0; k0 < PL; k0 += 8) {
        __syncthreads();
        sA[lrow][lk + 0] = f2tf32(av.x);
        sA[lrow][lk + 1] = f2tf32(av.y);
        sA[lrow][lk + 2] = f2tf32(av.z);
        sA[lrow][lk + 3] = f2tf32(av.w);
        sB[lrow][lk + 0] = f2tf32(bv.x);
        sB[lrow][lk + 1] = f2tf32(bv.y);
        sB[lrow][lk + 2] = f2tf32(bv.z);
        sB[lrow][lk + 3] = f2tf32(bv.w);
        __syncthreads();

        if (k0 + 8 < PL) {
            av = *(const float4*)(aptr + k0 + 8);
            bv = *(const float4*)(bptr + k0 + 8);
        }

        uint32_t af[2][4];
        #pragma unroll
        for (int mt = 0; mt < 2; ++mt) {
            int m = wm * 32 + mt * 16;
            af[mt][0] = sA[m + g][tg];
            af[mt][1] = sA[m + g + 8][tg];
            af[mt][2] = sA[m + g][tg + 4];
            af[mt][3] = sA[m + g + 8][tg + 4];
        }
        uint32_t bf[8][2];
        #pragma unroll
        for (int nt = 0; nt < 8; ++nt) {
            int n = wn * 64 + nt * 8 + g;
            bf[nt][0] = sB[n][tg];
            bf[nt][1] = sB[n][tg + 4];
        }
        #pragma unroll
        for (int mt = 0; mt < 2; ++mt)
            #pragma unroll
            for (int nt = 0; nt < 8; ++nt)
                mma_tf32(acc[mt][nt], af[mt], bf[nt], acc[mt][nt]);
    }

    // epilogue
    #pragma unroll
    for (int mt = 0; mt < 2; ++mt) {
        #pragma unroll
        for (int h = 0; h < 2; ++h) {
            int r = row0 + wm * 32 + mt * 16 + g + h * 8;
            float mv = g_mean[r], iv = g_inv[r];
            int rbc = r / PP, rp = r % PP;
            int sid = subj[rbc >> 6];
            const float* gn = gain + (size_t)sid * EE;
            const float* pe = pos + (size_t)rp * EE;
            float* orow = emb + (size_t)r * EE;
            #pragma unroll
            for (int nt = 0; nt < 8; ++nt) {
                int d = n0 + wn * 64 + nt * 8 + 2 * tg;
                float c0 = acc[mt][nt][h * 2 + 0];
                float c1 = acc[mt][nt][h * 2 + 1];
                float v0 = (iv * (c0 - mv * g_wsum[d])     + bias[d]     + pe[d])     * gn[d];
                float v1 = (iv * (c1 - mv * g_wsum[d + 1]) + bias[d + 1] + pe[d + 1]) * gn[d + 1];
                *(float2*)(orow + d) = make_float2(v0, v1);
            }
        }
    }
}

// ---------------- JAX threefry2x32, partitionable mode ----------------
__device__ __forceinline__ void threefry(uint32_t k0, uint32_t k1,
                                         uint32_t x0, uint32_t x1,
                                         uint32_t& o0, uint32_t& o1) {
    uint32_t ks2 = k0 ^ k1 ^ 0x1BD11BDAu;
    x0 += k0; x1 += k1;
#define TF_RND(r) { x0 += x1; x1 = (x1 << r) | (x1 >> (32 - r)); x1 ^= x0; }
    TF_RND(13) TF_RND(15) TF_RND(26) TF_RND(6)  x0 += k1;  x1 += ks2 + 1u;
    TF_RND(17) TF_RND(29) TF_RND(16) TF_RND(24) x0 += ks2; x1 += k0 + 2u;
    TF_RND(13) TF_RND(15) TF_RND(26) TF_RND(6)  x0 += k0;  x1 += k1 + 3u;
    TF_RND(17) TF_RND(29) TF_RND(16) TF_RND(24) x0 += k1;  x1 += ks2 + 4u;
    TF_RND(13) TF_RND(15) TF_RND(26) TF_RND(6)  x0 += ks2; x1 += k0 + 5u;
#undef TF_RND
    o0 = x0; o1 = x1;
}

__device__ __forceinline__ uint32_t prf32(uint32_t k0, uint32_t k1, uint32_t i) {
    uint32_t o0, o1;
    threefry(k0, k1, 0u, i, o0, o1);
    return o0 ^ o1;
}

__device__ __forceinline__ float u01(uint32_t bits) {
    return __uint_as_float((bits >> 9) | 0x3f800000u) - 1.0f;
}

__global__ void mask_kernel(float* __restrict__ mout) {
    int row = blockIdx.x * blockDim.x + threadIdx.x;
    if (row >= BB * CC) return;
    uint32_t k1a, k1b, k2a, k2b;
    threefry(0u, 42u, 0u, 0u, k1a, k1b);
    threefry(0u, 42u, 0u, 1u, k2a, k2b);

    float r0 = u01(prf32(k2a, k2b, (uint32_t)(row * 3 + 0)));
    float r1 = u01(prf32(k2a, k2b, (uint32_t)(row * 3 + 1)));
    float r2 = u01(prf32(k2a, k2b, (uint32_t)(row * 3 + 2)));

    bool m[PP];
    #pragma unroll
    for (int j = 0; j < PP; ++j)
        m[j] = u01(prf32(k1a, k1b, (uint32_t)(row * PP + j))) < 0.1f;

    if (r0 < 0.5f)  { for (int j = PP - 1; j >= 1; --j) m[j] = m[j] | m[j - 1]; }
    if (r1 < 0.5f)  { for (int j = 0; j < PP - 1; ++j) m[j] = m[j] | m[j + 1]; }
    if (r2 < 0.25f) { for (int j = 0; j < PP - 1; ++j) m[j] = m[j] | m[j + 1]; }

    float* dst = mout + (size_t)row * PP;
    #pragma unroll
    for (int j = 0; j < PP; ++j) dst[j] = m[j] ? 1.0f : 0.0f;
}

// ---------------- launch ----------------
extern "C" void kernel_launch(void* const* d_in, const int* in_sizes, int n_in,
                              void* d_out, int out_size) {
    const float* x    = (const float*)d_in[0];
    const int*   subj = (const int*)  d_in[1];
    const float* W    = (const float*)d_in[2];
    const float* bias = (const float*)d_in[3];
    const float* pos  = (const float*)d_in[4];
    const float* gain = (const float*)d_in[5];

    float* out      = (float*)d_out;
    float* emb      = out;                               // 77824*512
    float* patches  = emb + (size_t)NROWS * EE;          // 77824*200
    float* mfloat   = patches + (size_t)NROWS * PL;      // 77824
    float* mean_out = mfloat + NROWS;                    // 77824
    float* std_out  = mean_out + NROWS;                  // 77824

    wsum_kernel<<<2, 256>>>(W);
    stats_kernel<<<NROWS / 8, 256>>>(x, patches, mean_out, std_out);
    dim3 g(NROWS / BM, EE / BN);
    gemm_tc_kernel<<<g, 256>>>(x, W, bias, pos, subj, gain, emb);
    mask_kernel<<<(BB * CC) / 256, 256>>>(mfloat);
}

// round 5
// speedup vs baseline: 1.9103x; 1.2188x over previous
#include <cuda_runtime.h>
#include <cstdint>

// Problem constants
#define BB 64
#define CC 64
#define TT 2000
#define PL 200
#define STRD 100
#define EE 512
#define PP 19
#define NROWS (BB*CC*PP)   // 77824
#define EPSV 1e-5f

// Scratch (allowed: __device__ globals)
__device__ float g_mean[NROWS];
__device__ float g_inv[NROWS];
__device__ float g_wsum[EE];

// ---------------- wsum: rowsum of W over l ----------------
__global__ void wsum_kernel(const float* __restrict__ W) {
    int d = blockIdx.x * blockDim.x + threadIdx.x;
    if (d < EE) {
        const float* wr = W + (size_t)d * PL;
        float s = 0.f;
        #pragma unroll 8
        for (int l = 0; l < PL; ++l) s += wr[l];
        g_wsum[d] = s;
    }
}

// ---------------- stats + patches copy ----------------
__global__ void stats_kernel(const float* __restrict__ x,
                             float* __restrict__ patches,
                             float* __restrict__ mean_out,
                             float* __restrict__ std_out) {
    int warp = (blockIdx.x * blockDim.x + threadIdx.x) >> 5;
    int lane = threadIdx.x & 31;
    if (warp >= NROWS) return;
    int bc = warp / PP;
    int p  = warp % PP;
    const float* src = x + (size_t)bc * TT + p * STRD;
    float* dst = patches + (size_t)warp * PL;

    float s = 0.f, s2 = 0.f;
    #pragma unroll
    for (int i = 0; i < 7; ++i) {
        int l = lane + i * 32;
        if (l < PL) {
            float v = src[l];
            s += v; s2 += v * v;
            dst[l] = v;
        }
    }
    #pragma unroll
    for (int off = 16; off; off >>= 1) {
        s  += __shfl_xor_sync(0xffffffffu, s,  off);
        s2 += __shfl_xor_sync(0xffffffffu, s2, off);
    }
    if (lane == 0) {
        float mean = s * (1.f / PL);
        float var  = (s2 - s * mean) * (1.f / (PL - 1));
        float sd   = sqrtf(fmaxf(var, 0.f));
        mean_out[warp] = mean;
        std_out[warp]  = sd;
        g_mean[warp] = mean;
        g_inv[warp]  = 1.f / (sd + EPSV);
    }
}

// ---------------- tf32 tensor-core GEMM ----------------
__device__ __forceinline__ uint32_t f2tf32(float x) {
    uint32_t r;
    asm("cvt.rna.tf32.f32 %0, %1;" : "=r"(r) : "f"(x));
    return r;
}

__device__ __forceinline__ void mma_tf32(float* d, const uint32_t* a,
                                         const uint32_t* b, const float* c) {
    asm volatile(
        "mma.sync.aligned.m16n8k8.row.col.f32.tf32.tf32.f32 "
        "{%0,%1,%2,%3}, {%4,%5,%6,%7}, {%8,%9}, {%10,%11,%12,%13};\n"
        : "=f"(d[0]), "=f"(d[1]), "=f"(d[2]), "=f"(d[3])
        : "r"(a[0]), "r"(a[1]), "r"(a[2]), "r"(a[3]),
          "r"(b[0]), "r"(b[1]),
          "f"(c[0]), "f"(c[1]), "f"(c[2]), "f"(c[3]));
}

#define BM 128
#define BN 128
#define BK 40
#define BKP 44   // 44 % 32 == 12 -> conflict-free STS.128 and fragment LDS

__global__ __launch_bounds__(256, 2) void gemm_tc_kernel(
    const float* __restrict__ x, const float* __restrict__ W,
    const float* __restrict__ bias, const float* __restrict__ pos,
    const int* __restrict__ subj, const float* __restrict__ gain,
    float* __restrict__ emb)
{
    __shared__ float sA[BM][BKP];
    __shared__ float sB[BN][BKP];

    const int tid  = threadIdx.x;
    const int wid  = tid >> 5;
    const int lane = tid & 31;
    const int g    = lane >> 2;   // 0..7
    const int tg   = lane & 3;    // 0..3
    const int wm   = wid >> 1;    // 0..3 : warp M tile (32 rows)
    const int wn   = wid & 1;     // 0..1 : warp N tile (64 cols)

    const int row0 = blockIdx.x * BM;
    const int n0   = blockIdx.y * BN;

    // global loaders: thread t<128 -> A row t; t>=128 -> B row t-128
    const int lrow = tid & 127;
    const bool isA = (tid < 128);
    const float* srcp;
    if (isA) {
        int arow = row0 + lrow;
        int abc = arow / PP, ap = arow % PP;
        srcp = x + (size_t)abc * TT + ap * STRD;
    } else {
        srcp = W + (size_t)(n0 + lrow) * PL;
    }
    float* dstp = isA ? &sA[lrow][0] : &sB[lrow][0];

    float acc[2][8][4];
    #pragma unroll
    for (int mt = 0; mt < 2; ++mt)
        #pragma unroll
        for (int nt = 0; nt < 8; ++nt)
            #pragma unroll
            for (int q = 0; q < 4; ++q) acc[mt][nt][q] = 0.f;

    #pragma unroll 1
    for (int s = 0; s < 5; ++s) {
        __syncthreads();
        // load stage: 40 floats = 10 float4 per thread
        #pragma unroll
        for (int j = 0; j < 10; ++j) {
            float4 v = *(const float4*)(srcp + s * BK + j * 4);
            *(float4*)(dstp + j * 4) = v;
        }
        __syncthreads();

        #pragma unroll
        for (int kk = 0; kk < 5; ++kk) {
            const int kb = kk * 8;
            uint32_t af[2][4];
            #pragma unroll
            for (int mt = 0; mt < 2; ++mt) {
                int m = wm * 32 + mt * 16;
                af[mt][0] = f2tf32(sA[m + g][kb + tg]);
                af[mt][1] = f2tf32(sA[m + g + 8][kb + tg]);
                af[mt][2] = f2tf32(sA[m + g][kb + tg + 4]);
                af[mt][3] = f2tf32(sA[m + g + 8][kb + tg + 4]);
            }
            uint32_t bf[8][2];
            #pragma unroll
            for (int nt = 0; nt < 8; ++nt) {
                int n = wn * 64 + nt * 8 + g;
                bf[nt][0] = f2tf32(sB[n][kb + tg]);
                bf[nt][1] = f2tf32(sB[n][kb + tg + 4]);
            }
            #pragma unroll
            for (int mt = 0; mt < 2; ++mt)
                #pragma unroll
                for (int nt = 0; nt < 8; ++nt)
                    mma_tf32(acc[mt][nt], af[mt], bf[nt], acc[mt][nt]);
        }
    }

    // epilogue
    #pragma unroll
    for (int mt = 0; mt < 2; ++mt) {
        #pragma unroll
        for (int h = 0; h < 2; ++h) {
            int r = row0 + wm * 32 + mt * 16 + g + h * 8;
            float mv = g_mean[r], iv = g_inv[r];
            int rbc = r / PP, rp = r % PP;
            int sid = subj[rbc >> 6];
            const float* gn = gain + (size_t)sid * EE;
            const float* pe = pos + (size_t)rp * EE;
            float* orow = emb + (size_t)r * EE;
            #pragma unroll
            for (int nt = 0; nt < 8; ++nt) {
                int d = n0 + wn * 64 + nt * 8 + 2 * tg;
                float c0 = acc[mt][nt][h * 2 + 0];
                float c1 = acc[mt][nt][h * 2 + 1];
                float v0 = (iv * (c0 - mv * g_wsum[d])     + bias[d]     + pe[d])     * gn[d];
                float v1 = (iv * (c1 - mv * g_wsum[d + 1]) + bias[d + 1] + pe[d + 1]) * gn[d + 1];
                *(float2*)(orow + d) = make_float2(v0, v1);
            }
        }
    }
}

// ---------------- JAX threefry2x32, partitionable mode ----------------
__device__ __forceinline__ void threefry(uint32_t k0, uint32_t k1,
                                         uint32_t x0, uint32_t x1,
                                         uint32_t& o0, uint32_t& o1) {
    uint32_t ks2 = k0 ^ k1 ^ 0x1BD11BDAu;
    x0 += k0; x1 += k1;
#define TF_RND(r) { x0 += x1; x1 = (x1 << r) | (x1 >> (32 - r)); x1 ^= x0; }
    TF_RND(13) TF_RND(15) TF_RND(26) TF_RND(6)  x0 += k1;  x1 += ks2 + 1u;
    TF_RND(17) TF_RND(29) TF_RND(16) TF_RND(24) x0 += ks2; x1 += k0 + 2u;
    TF_RND(13) TF_RND(15) TF_RND(26) TF_RND(6)  x0 += k0;  x1 += k1 + 3u;
    TF_RND(17) TF_RND(29) TF_RND(16) TF_RND(24) x0 += k1;  x1 += ks2 + 4u;
    TF_RND(13) TF_RND(15) TF_RND(26) TF_RND(6)  x0 += ks2; x1 += k0 + 5u;
#undef TF_RND
    o0 = x0; o1 = x1;
}

__device__ __forceinline__ uint32_t prf32(uint32_t k0, uint32_t k1, uint32_t i) {
    uint32_t o0, o1;
    threefry(k0, k1, 0u, i, o0, o1);
    return o0 ^ o1;
}

__device__ __forceinline__ float u01(uint32_t bits) {
    return __uint_as_float((bits >> 9) | 0x3f800000u) - 1.0f;
}

__global__ void mask_kernel(float* __restrict__ mout) {
    int row = blockIdx.x * blockDim.x + threadIdx.x;
    if (row >= BB * CC) return;
    uint32_t k1a, k1b, k2a, k2b;
    threefry(0u, 42u, 0u, 0u, k1a, k1b);
    threefry(0u, 42u, 0u, 1u, k2a, k2b);

    float r0 = u01(prf32(k2a, k2b, (uint32_t)(row * 3 + 0)));
    float r1 = u01(prf32(k2a, k2b, (uint32_t)(row * 3 + 1)));
    float r2 = u01(prf32(k2a, k2b, (uint32_t)(row * 3 + 2)));

    bool m[PP];
    #pragma unroll
    for (int j = 0; j < PP; ++j)
        m[j] = u01(prf32(k1a, k1b, (uint32_t)(row * PP + j))) < 0.1f;

    if (r0 < 0.5f)  { for (int j = PP - 1; j >= 1; --j) m[j] = m[j] | m[j - 1]; }
    if (r1 < 0.5f)  { for (int j = 0; j < PP - 1; ++j) m[j] = m[j] | m[j + 1]; }
    if (r2 < 0.25f) { for (int j = 0; j < PP - 1; ++j) m[j] = m[j] | m[j + 1]; }

    float* dst = mout + (size_t)row * PP;
    #pragma unroll
    for (int j = 0; j < PP; ++j) dst[j] = m[j] ? 1.0f : 0.0f;
}

// ---------------- launch ----------------
extern "C" void kernel_launch(void* const* d_in, const int* in_sizes, int n_in,
                              void* d_out, int out_size) {
    const float* x    = (const float*)d_in[0];
    const int*   subj = (const int*)  d_in[1];
    const float* W    = (const float*)d_in[2];
    const float* bias = (const float*)d_in[3];
    const float* pos  = (const float*)d_in[4];
    const float* gain = (const float*)d_in[5];

    float* out      = (float*)d_out;
    float* emb      = out;                               // 77824*512
    float* patches  = emb + (size_t)NROWS * EE;          // 77824*200
    float* mfloat   = patches + (size_t)NROWS * PL;      // 77824
    float* mean_out = mfloat + NROWS;                    // 77824
    float* std_out  = mean_out + NROWS;                  // 77824

    wsum_kernel<<<2, 256>>>(W);
    stats_kernel<<<NROWS / 8, 256>>>(x, patches, mean_out, std_out);
    dim3 g(NROWS / BM, EE / BN);
    gemm_tc_kernel<<<g, 256>>>(x, W, bias, pos, subj, gain, emb);
    mask_kernel<<<(BB * CC) / 256, 256>>>(mfloat);
}